// round 8
// baseline (speedup 1.0000x reference)
#include <cuda_runtime.h>

#define NPTS    2048
#define NPAIR   (NPTS/2)
#define UPR     10
#define NJIT    (NPTS*UPR)           // 20480
#define QTOT    (NJIT + NPTS)        // 22528
#define KNN     5
#define T1      256
#define CAP     224                  // candidate capacity per parent-task
#define NPB     8                    // parent tasks (warps) per block
#define PBLK    (2*NPTS/NPB)         // 512 parent blocks (256 per cloud)
#define SBLK    64                   // src-query blocks (32 per cloud)
#define NB2     (QTOT/256)           // 88
#define EPS_D   1e-8f
#define EPS_N   1e-10f
#define BETA    3.0f
#define STDV    0.05f
#define IDXMASK 0xFFFFF800u

__device__ float4 g_grad[2][QTOT];
__device__ int    g_cand[2*NPTS][CAP];   // candidate point indices per (cloud,parent)
__device__ int    g_cnt[2*NPTS];
__device__ float  g_partial[NB2];

// ---- helpers ---------------------------------------------------------------
__device__ __forceinline__ void ins5key(int key, int& s0, int& s1, int& s2, int& s3, int& s4) {
    s4 = key;
    int a;
    a = min(s3, s4); s4 = max(s3, s4); s3 = a;
    a = min(s2, s3); s3 = max(s2, s3); s2 = a;
    a = min(s1, s2); s2 = max(s1, s2); s1 = a;
    a = min(s0, s1); s1 = max(s0, s1); s0 = a;
}
__device__ __forceinline__ void ins5v(float r, float& s0, float& s1, float& s2, float& s3, float& s4) {
    s4 = r;
    float a;
    a = fminf(s3, s4); s4 = fmaxf(s3, s4); s3 = a;
    a = fminf(s2, s3); s3 = fmaxf(s2, s3); s2 = a;
    a = fminf(s1, s2); s2 = fmaxf(s1, s2); s1 = a;
    a = fminf(s0, s1); s1 = fmaxf(s0, s1); s0 = a;
}
__device__ __forceinline__ void merge_keys(int msk, int& s0, int& s1, int& s2, int& s3, int& s4) {
    int o0 = __shfl_xor_sync(0xFFFFFFFFu, s0, msk);
    int o1 = __shfl_xor_sync(0xFFFFFFFFu, s1, msk);
    int o2 = __shfl_xor_sync(0xFFFFFFFFu, s2, msk);
    int o3 = __shfl_xor_sync(0xFFFFFFFFu, s3, msk);
    int o4 = __shfl_xor_sync(0xFFFFFFFFu, s4, msk);
    if (o0 < s4) ins5key(o0, s0, s1, s2, s3, s4);
    if (o1 < s4) ins5key(o1, s0, s1, s2, s3, s4);
    if (o2 < s4) ins5key(o2, s0, s1, s2, s3, s4);
    if (o3 < s4) ins5key(o3, s0, s1, s2, s3, s4);
    if (o4 < s4) ins5key(o4, s0, s1, s2, s3, s4);
}
__device__ __forceinline__ void merge_vals(int msk, float& s0, float& s1, float& s2, float& s3, float& s4) {
    float o0 = __shfl_xor_sync(0xFFFFFFFFu, s0, msk);
    float o1 = __shfl_xor_sync(0xFFFFFFFFu, s1, msk);
    float o2 = __shfl_xor_sync(0xFFFFFFFFu, s2, msk);
    float o3 = __shfl_xor_sync(0xFFFFFFFFu, s3, msk);
    float o4 = __shfl_xor_sync(0xFFFFFFFFu, s4, msk);
    if (o0 < s4) ins5v(o0, s0, s1, s2, s3, s4);
    if (o1 < s4) ins5v(o1, s0, s1, s2, s3, s4);
    if (o2 < s4) ins5v(o2, s0, s1, s2, s3, s4);
    if (o3 < s4) ins5v(o3, s0, s1, s2, s3, s4);
    if (o4 < s4) ins5v(o4, s0, s1, s2, s3, s4);
}
__device__ __forceinline__ unsigned long long packf2(float lo, float hi) {
    unsigned long long r;
    asm("mov.b64 %0, {%1, %2};" : "=l"(r) : "f"(lo), "f"(hi));
    return r;
}
__device__ __forceinline__ void pair_r(const float4* __restrict__ sC, int pj,
                                       unsigned long long qxp, unsigned long long qyp,
                                       unsigned long long qzp, float& r0, float& r1) {
    float4 a = sC[2 * pj];       // {x0,x1,y0,y1}
    float4 b = sC[2 * pj + 1];   // {z0,z1,w0,w1}
    unsigned long long xx = packf2(a.x, a.y);
    unsigned long long yy = packf2(a.z, a.w);
    unsigned long long zz = packf2(b.x, b.y);
    unsigned long long ww = packf2(b.z, b.w);
    unsigned long long r01;
    asm("fma.rn.f32x2 %0, %1, %2, %3;" : "=l"(r01) : "l"(zz), "l"(qzp), "l"(ww));
    asm("fma.rn.f32x2 %0, %1, %2, %3;" : "=l"(r01) : "l"(yy), "l"(qyp), "l"(r01));
    asm("fma.rn.f32x2 %0, %1, %2, %3;" : "=l"(r01) : "l"(xx), "l"(qxp), "l"(r01));
    asm("mov.b64 {%0, %1}, %2;" : "=f"(r0), "=f"(r1) : "l"(r01));
}

// ---- kernel 1: parent candidate-collection + src-query exact kNN -----------
__global__ __launch_bounds__(T1)
void parent_scan(const float* __restrict__ src,
                 const float* __restrict__ tgt,
                 const float* __restrict__ noise)
{
    __shared__ float4 sC[NPTS];      // pair-packed cloud, 32 KB
    __shared__ int    sCnt[NPB];

    const int tid = threadIdx.x;
    const int b   = blockIdx.x;
    const bool isParent = (b < PBLK);
    const int cloud = isParent ? (b >> 8) : ((b - PBLK) >> 5);
    const float* __restrict__ pts = cloud ? src : tgt;

    for (int i = tid; i < NPTS; i += T1) {
        float x = pts[3*i], y = pts[3*i+1], z = pts[3*i+2];
        float w = fmaf(x, x, fmaf(y, y, z * z));
        int pj = i >> 1, h = i & 1;
        float* base = (float*)&sC[2 * pj];
        base[0 + h] = x; base[2 + h] = y; base[4 + h] = z; base[6 + h] = w;
    }
    __syncthreads();

    if (isParent) {
        // ---- whole-warp parent task ----
        const int w    = tid >> 5;
        const int lane = tid & 31;
        const int m    = (b & 255) * NPB + w;         // parent (tgt point) index
        const int t    = cloud * NPTS + m;            // task id

        float px = tgt[3*m], py = tgt[3*m+1], pz = tgt[3*m+2];
        const float p2  = fmaf(px, px, fmaf(py, py, pz * pz));
        const float px2 = -2.0f * px, py2 = -2.0f * py, pz2 = -2.0f * pz;
        const unsigned long long qxp = packf2(px2, px2);
        const unsigned long long qyp = packf2(py2, py2);
        const unsigned long long qzp = packf2(pz2, pz2);

        // delta-max over this parent's 10 siblings
        float dl = 0.f;
        if (lane < UPR) {
            int nb = 3 * (m * UPR + lane);
            float nx = noise[nb], ny = noise[nb+1], nz = noise[nb+2];
            dl = STDV * sqrtf(fmaf(nx, nx, fmaf(ny, ny, nz * nz)));
        }
#pragma unroll
        for (int o = 16; o > 0; o >>= 1)
            dl = fmaxf(dl, __shfl_xor_sync(0xFFFFFFFFu, dl, o));
        dl = fmaf(dl, 1.001f, 1e-6f);

        // pass 1: exact top-5 r-values of the parent
        float s0 = 3e38f, s1 = 3e38f, s2 = 3e38f, s3 = 3e38f, s4 = 3e38f;
#pragma unroll 4
        for (int k = 0; k < NPAIR / 32; ++k) {
            int pj = (k << 5) + lane;
            float r0, r1;
            pair_r(sC, pj, qxp, qyp, qzp, r0, r1);
            if (fminf(r0, r1) < s4) {
                if (r0 < s4) ins5v(r0, s0, s1, s2, s3, s4);
                if (r1 < s4) ins5v(r1, s0, s1, s2, s3, s4);
            }
        }
        merge_vals(1, s0, s1, s2, s3, s4);
        merge_vals(2, s0, s1, s2, s3, s4);
        merge_vals(4, s0, s1, s2, s3, s4);
        merge_vals(8, s0, s1, s2, s3, s4);
        merge_vals(16, s0, s1, s2, s3, s4);

        float d5 = sqrtf(fmaxf(s4 + p2, 0.0f));
        float R  = fmaf(d5, 1.0005f, dl + dl);     // d5 margin + 2*deltamax
        float thrC = fmaf(R, R, 1e-7f) - p2;       // r-space collection threshold

        if (lane == 0) sCnt[w] = 0;
        __syncwarp();

        // pass 2: collect candidates within R of parent
#pragma unroll 4
        for (int k = 0; k < NPAIR / 32; ++k) {
            int pj = (k << 5) + lane;
            float r0, r1;
            pair_r(sC, pj, qxp, qyp, qzp, r0, r1);
            if (r0 <= thrC) {
                int sl = atomicAdd(&sCnt[w], 1);
                if (sl < CAP) g_cand[t][sl] = 2 * pj;
            }
            if (r1 <= thrC) {
                int sl = atomicAdd(&sCnt[w], 1);
                if (sl < CAP) g_cand[t][sl] = 2 * pj + 1;
            }
        }
        __syncwarp();
        if (lane == 0) g_cnt[t] = sCnt[w];
    } else {
        // ---- src-point queries: exact R7 path, SPLIT=4 ----
        const int local = b - PBLK;
        const int sq  = (local & 31) * 64 + (tid >> 2);
        const int par = tid & 3;

        float qx = src[3*sq], qy = src[3*sq+1], qz = src[3*sq+2];
        const float qx2 = -2.0f * qx, qy2 = -2.0f * qy, qz2 = -2.0f * qz;
        const float q2  = fmaf(qx, qx, fmaf(qy, qy, qz * qz));
        const unsigned long long qxp = packf2(qx2, qx2);
        const unsigned long long qyp = packf2(qy2, qy2);
        const unsigned long long qzp = packf2(qz2, qz2);

        int s0 = 0x7F000000, s1 = 0x7F000001, s2 = 0x7F000002,
            s3 = 0x7F000003, s4 = 0x7F000004;
        float thr = __int_as_float(s4) - q2;

#pragma unroll 4
        for (int k = 0; k < NPAIR / 4; ++k) {
            int pj = (k << 2) + par;
            float r0, r1;
            pair_r(sC, pj, qxp, qyp, qzp, r0, r1);
            if (fminf(r0, r1) < thr) {
                if (r0 < thr) {
                    float d2 = r0 + q2;
                    int key = (int)((__float_as_uint(d2) & IDXMASK) | (unsigned)(2 * pj));
                    ins5key(key, s0, s1, s2, s3, s4);
                    thr = __int_as_float(s4) - q2;
                }
                if (r1 < thr) {
                    float d2 = r1 + q2;
                    int key = (int)((__float_as_uint(d2) & IDXMASK) | (unsigned)(2 * pj + 1));
                    ins5key(key, s0, s1, s2, s3, s4);
                    thr = __int_as_float(s4) - q2;
                }
            }
        }
        merge_keys(1, s0, s1, s2, s3, s4);
        merge_keys(2, s0, s1, s2, s3, s4);

        if (par == 0) {
            float aw = 0.f, gx = 0.f, gy = 0.f, gz = 0.f;
            int keys[KNN] = {s0, s1, s2, s3, s4};
#pragma unroll
            for (int kk = 0; kk < KNN; ++kk) {
                int idx = keys[kk] & 2047;
                int pj = idx >> 1, h = idx & 1;
                const float* base = (const float*)&sC[2 * pj];
                float dx = qx - base[0 + h], dy = qy - base[2 + h], dz = qz - base[4 + h];
                float d2 = fmaf(dx, dx, fmaf(dy, dy, dz * dz));
                float ww = 1.0f / (d2 + EPS_D);
                aw += ww;
                gx = fmaf(dx, ww, gx);
                gy = fmaf(dy, ww, gy);
                gz = fmaf(dz, ww, gz);
            }
            float inv = 1.0f / aw;
            g_grad[cloud][NJIT + sq] = make_float4(gx * inv, gy * inv, gz * inv, 0.f);
        }
    }
}

// ---- kernel 2: jittered queries over parent candidates ---------------------
__global__ __launch_bounds__(T1)
void sibling_eval(const float* __restrict__ src,
                  const float* __restrict__ tgt,
                  const float* __restrict__ noise)
{
    const int half = blockIdx.x >= (NJIT / T1);              // 0..79 cloud0, 80..159 cloud1
    const int cloud = half;
    const int qi = (blockIdx.x - half * (NJIT / T1)) * T1 + threadIdx.x;   // 0..NJIT-1
    const int m  = qi / UPR;
    const int t  = cloud * NPTS + m;
    const float* __restrict__ pts = cloud ? src : tgt;

    float qx = fmaf(noise[3*qi + 0], STDV, tgt[3*m + 0]);
    float qy = fmaf(noise[3*qi + 1], STDV, tgt[3*m + 1]);
    float qz = fmaf(noise[3*qi + 2], STDV, tgt[3*m + 2]);
    const float qx2 = -2.0f * qx, qy2 = -2.0f * qy, qz2 = -2.0f * qz;
    const float q2  = fmaf(qx, qx, fmaf(qy, qy, qz * qz));

    int s0 = 0x7F000000, s1 = 0x7F000001, s2 = 0x7F000002,
        s3 = 0x7F000003, s4 = 0x7F000004;
    float thrD = __int_as_float(s4);

    const int cnt = g_cnt[t];
    if (cnt <= CAP) {
        for (int i = 0; i < cnt; ++i) {
            int idx = g_cand[t][i];
            float x = pts[3*idx], y = pts[3*idx+1], z = pts[3*idx+2];
            float w = fmaf(x, x, fmaf(y, y, z * z));
            float r = fmaf(x, qx2, fmaf(y, qy2, fmaf(z, qz2, w)));
            float d2 = r + q2;
            if (d2 < thrD) {
                int key = (int)((__float_as_uint(d2) & IDXMASK) | (unsigned)idx);
                ins5key(key, s0, s1, s2, s3, s4);
                thrD = __int_as_float(s4);
            }
        }
    } else {
        // overflow fallback: exact full scan (rare/never)
        for (int idx = 0; idx < NPTS; ++idx) {
            float x = pts[3*idx], y = pts[3*idx+1], z = pts[3*idx+2];
            float w = fmaf(x, x, fmaf(y, y, z * z));
            float r = fmaf(x, qx2, fmaf(y, qy2, fmaf(z, qz2, w)));
            float d2 = r + q2;
            if (d2 < thrD) {
                int key = (int)((__float_as_uint(d2) & IDXMASK) | (unsigned)idx);
                ins5key(key, s0, s1, s2, s3, s4);
                thrD = __int_as_float(s4);
            }
        }
    }

    float aw = 0.f, gx = 0.f, gy = 0.f, gz = 0.f;
    int keys[KNN] = {s0, s1, s2, s3, s4};
#pragma unroll
    for (int kk = 0; kk < KNN; ++kk) {
        int idx = keys[kk] & 2047;
        float dx = qx - pts[3*idx], dy = qy - pts[3*idx+1], dz = qz - pts[3*idx+2];
        float d2 = fmaf(dx, dx, fmaf(dy, dy, dz * dz));
        float w  = 1.0f / (d2 + EPS_D);
        aw += w;
        gx = fmaf(dx, w, gx);
        gy = fmaf(dy, w, gy);
        gz = fmaf(dz, w, gz);
    }
    float inv = 1.0f / aw;
    g_grad[cloud][qi] = make_float4(gx * inv, gy * inv, gz * inv, 0.f);
}

// ---- tails ------------------------------------------------------------------
__global__ __launch_bounds__(256)
void combine_kernel()
{
    __shared__ float sh[8];
    const int tid = threadIdx.x;
    const int qi  = blockIdx.x * 256 + tid;

    float4 gT = g_grad[0][qi];
    float4 gS = g_grad[1][qi];

    float axT = gT.x + EPS_N, ayT = gT.y + EPS_N, azT = gT.z + EPS_N;
    float axS = gS.x + EPS_N, ayS = gS.y + EPS_N, azS = gS.z + EPS_N;
    float uT = sqrtf(fmaf(axT, axT, fmaf(ayT, ayT, azT * azT)));
    float uS = sqrtf(fmaf(axS, axS, fmaf(ayS, ayS, azS * azS)));

    float e1 = fabsf(uT - uS);
    float e2 = fabsf(gS.x - gT.x) + fabsf(gS.y - gT.y) + fabsf(gS.z - gT.z);
    float tt = e1 + e2;
    float v  = tt * __expf(-BETA * tt);

#pragma unroll
    for (int o = 16; o > 0; o >>= 1) v += __shfl_down_sync(0xFFFFFFFFu, v, o);
    if ((tid & 31) == 0) sh[tid >> 5] = v;
    __syncthreads();
    if (tid == 0) {
        float s = 0.f;
#pragma unroll
        for (int w = 0; w < 8; ++w) s += sh[w];
        g_partial[blockIdx.x] = s;
    }
}

__global__ void final_reduce(float* __restrict__ out)
{
    __shared__ float sh[4];
    int tid = threadIdx.x;   // 128
    float v = (tid < NB2) ? g_partial[tid] : 0.f;
#pragma unroll
    for (int o = 16; o > 0; o >>= 1) v += __shfl_down_sync(0xFFFFFFFFu, v, o);
    if ((tid & 31) == 0) sh[tid >> 5] = v;
    __syncthreads();
    if (tid == 0) {
        float s = sh[0] + sh[1] + sh[2] + sh[3];
        out[0] = s * (1.0f / (float)QTOT);
    }
}

extern "C" void kernel_launch(void* const* d_in, const int* in_sizes, int n_in,
                              void* d_out, int out_size)
{
    const float* src   = (const float*)d_in[0];
    const float* tgt   = (const float*)d_in[1];
    const float* noise = (const float*)d_in[2];
    (void)in_sizes; (void)n_in; (void)out_size;

    parent_scan <<<PBLK + SBLK, T1>>>(src, tgt, noise);
    sibling_eval<<<2 * (NJIT / T1), T1>>>(src, tgt, noise);
    combine_kernel<<<NB2, 256>>>();
    final_reduce<<<1, 128>>>((float*)d_out);
}